// round 2
// baseline (speedup 1.0000x reference)
#include <cuda_runtime.h>

// Problem constants
#define NL   32
#define H    2048
#define R    64
#define BSZ  2048
#define HA   128            // h-chunk for proj phase
#define NCA  (H / HA)       // 16
#define HB   128            // h-chunk for delta phase
#define NCB  (H / HB)       // 16

// Scratch (device globals; no allocation allowed)
__device__ int   g_count[NL];
__device__ int   g_bucket[NL][BSZ];
__device__ float g_proj[BSZ][R];

// -------------------------------------------------------------------------
// 1) zero counters + proj accumulator (must run every launch: graph replays)
__global__ void init_kernel() {
    int idx = blockIdx.x * blockDim.x + threadIdx.x;
    if (idx < NL) g_count[idx] = 0;
    float* p = &g_proj[0][0];
    int stride = gridDim.x * blockDim.x;
    for (int i = idx; i < BSZ * R; i += stride) p[i] = 0.0f;
}

// -------------------------------------------------------------------------
// 2) group samples by layer
__global__ void bucket_kernel(const int* __restrict__ layer_ids) {
    int b = blockIdx.x * blockDim.x + threadIdx.x;
    if (b < BSZ) {
        int l = layer_ids[b];
        int pos = atomicAdd(&g_count[l], 1);
        g_bucket[l][pos] = b;
    }
}

// -------------------------------------------------------------------------
// 3) proj[b][r] += sum_{h in chunk} v[l][h][r] * z[b][h]
//    grid = (NL, NCA), block = 256 (64 r-lanes x 4 h-quarters)
__global__ __launch_bounds__(256) void proj_kernel(const float* __restrict__ z,
                                                   const float* __restrict__ v) {
    __shared__ float v_s[HA][R + 1];  // +1 pad: conflict-free for both access patterns
    __shared__ float z_s[HA];
    __shared__ float red[256];

    const int l  = blockIdx.x;
    const int h0 = blockIdx.y * HA;
    const int t  = threadIdx.x;

    // stage v chunk: gmem layout v[l][h][r] (r fastest) -> coalesced
    const float* vbase = v + ((size_t)l * H + h0) * R;
    for (int i = t; i < HA * R; i += 256) {
        v_s[i >> 6][i & 63] = vbase[i];
    }

    const int n = g_count[l];
    const int r = t & 63;
    const int q = t >> 6;
    const int hbase = q * 32;

    for (int s = 0; s < n; s++) {
        const int b = g_bucket[l][s];
        __syncthreads();                       // also covers v_s load on s==0
        if (t < HA / 4) {
            ((float4*)z_s)[t] = ((const float4*)(z + (size_t)b * H + h0))[t];
        }
        __syncthreads();

        float acc = 0.0f;
        #pragma unroll
        for (int i = 0; i < 32; i++) {
            acc += v_s[hbase + i][r] * z_s[hbase + i];
        }
        red[t] = acc;
        __syncthreads();
        if (t < 64) {
            float p = red[t] + red[t + 64] + red[t + 128] + red[t + 192];
            atomicAdd(&g_proj[b][t], p);
        }
    }
}

// -------------------------------------------------------------------------
// 4) out[b][h] = z[b][h] + sum_r u[l][h][r] * proj[b][r]
//    grid = (NL, NCB), block = 128 (one h per thread; u row in registers)
__global__ __launch_bounds__(128) void delta_kernel(const float* __restrict__ z,
                                                    const float* __restrict__ u,
                                                    float* __restrict__ out) {
    __shared__ float proj_s[R];

    const int l  = blockIdx.x;
    const int h0 = blockIdx.y * HB;
    const int t  = threadIdx.x;
    const int h  = h0 + t;

    // u row for this h into registers (16 x float4 = 64 floats)
    float4 u_r[16];
    const float4* ubase = (const float4*)(u + ((size_t)l * H + h) * R);
    #pragma unroll
    for (int i = 0; i < 16; i++) u_r[i] = ubase[i];

    const int n = g_count[l];
    for (int s = 0; s < n; s++) {
        const int b = g_bucket[l][s];
        __syncthreads();
        if (t < R / 4) {
            ((float4*)proj_s)[t] = ((const float4*)&g_proj[b][0])[t];
        }
        __syncthreads();

        float acc = 0.0f;
        #pragma unroll
        for (int i = 0; i < 16; i++) {
            float4 p = ((const float4*)proj_s)[i];
            acc += u_r[i].x * p.x + u_r[i].y * p.y + u_r[i].z * p.z + u_r[i].w * p.w;
        }
        const size_t idx = (size_t)b * H + h;
        out[idx] = z[idx] + acc;
    }
}

// -------------------------------------------------------------------------
extern "C" void kernel_launch(void* const* d_in, const int* in_sizes, int n_in,
                              void* d_out, int out_size) {
    const float* z         = (const float*)d_in[0];
    const int*   layer_ids = (const int*)d_in[1];
    const float* u         = (const float*)d_in[2];
    const float* v         = (const float*)d_in[3];
    float*       out       = (float*)d_out;

    init_kernel<<<256, 256>>>();
    bucket_kernel<<<(BSZ + 255) / 256, 256>>>(layer_ids);
    proj_kernel<<<dim3(NL, NCA), 256>>>(z, v);
    delta_kernel<<<dim3(NL, NCB), 128>>>(z, u, out);
}

// round 3
// speedup vs baseline: 1.2871x; 1.2871x over previous
#include <cuda_runtime.h>

// Problem constants
#define NL   32
#define H    2048
#define R    64
#define BSZ  2048

// proj phase tiling
#define HA      128          // h-chunk
#define NCA     (H / HA)     // 16
#define PSPLIT  2            // sample-parity split
#define SPQ     4            // samples per quarter per batch (16 samples/batch)

// delta phase tiling
#define HB      128
#define NCB     (H / HB)     // 16
#define DSPLIT  4            // sample split
#define DSB     8            // samples per batch per block

// Scratch (device globals; no allocation allowed)
__device__ int   g_count[NL];
__device__ int   g_bucket[NL][BSZ];
__device__ float g_proj[BSZ][R];

// -------------------------------------------------------------------------
// 1) zero counters + proj accumulator (graph replays -> must rerun)
__global__ void init_kernel() {
    int idx = blockIdx.x * blockDim.x + threadIdx.x;
    if (idx < NL) g_count[idx] = 0;
    float4* p = (float4*)&g_proj[0][0];
    int stride = gridDim.x * blockDim.x;
    for (int i = idx; i < BSZ * R / 4; i += stride) p[i] = make_float4(0.f, 0.f, 0.f, 0.f);
}

// -------------------------------------------------------------------------
// 2) group samples by layer
__global__ void bucket_kernel(const int* __restrict__ layer_ids) {
    int b = blockIdx.x * blockDim.x + threadIdx.x;
    if (b < BSZ) {
        int l = layer_ids[b];
        int pos = atomicAdd(&g_count[l], 1);
        g_bucket[l][pos] = b;
    }
}

// -------------------------------------------------------------------------
// 3) proj[b][r] += sum_{h in chunk} v[l][h][r] * z[b][h]
//    grid = (NL, NCA, PSPLIT), block = 256.
//    Thread (r = t&63, q = t>>6): holds v[l][h0..h0+127][r] in 128 registers,
//    accumulates SPQ samples of its group (g = q*PSPLIT + par) per batch.
//    No intra-block reduction: one atomicAdd per (sample, r) per chunk.
__global__ __launch_bounds__(256) void proj_kernel(const float* __restrict__ z,
                                                   const float* __restrict__ v) {
    __shared__ float v_s[HA][R];          // 32KB staging (coalesced gmem read)
    __shared__ float z_s[16][HA];         // 8KB: 16 samples x h-chunk
    __shared__ int   b_s[16];

    const int l   = blockIdx.x;
    const int h0  = blockIdx.y * HA;
    const int par = blockIdx.z;
    const int t   = threadIdx.x;
    const int r   = t & 63;
    const int q   = t >> 6;

    const int n = g_count[l];
    if (n == 0) return;

    // stage v chunk: coalesced float4
    {
        const float4* vb  = (const float4*)(v + ((size_t)l * H + h0) * R);
        float4*       vs4 = (float4*)&v_s[0][0];
        #pragma unroll
        for (int i = 0; i < (HA * R / 4) / 256; i++)
            vs4[t + i * 256] = vb[t + i * 256];
    }
    __syncthreads();

    // v column for this r into registers (conflict-free scalar LDS)
    float vr[HA];
    #pragma unroll
    for (int h = 0; h < HA; h++) vr[h] = v_s[h][r];

    const int nb = (n + 8 * SPQ - 1) / (8 * SPQ);   // 32 samples per batch

    for (int k = 0; k < nb; k++) {
        __syncthreads();            // protect b_s / z_s reuse
        if (t < 16) {
            int qq = t >> 2, ss = t & 3;
            int gg = qq * PSPLIT + par;
            int sg = gg + 8 * (k * SPQ + ss);
            b_s[t] = (sg < n) ? g_bucket[l][sg] : -1;
        }
        __syncthreads();
        // load 16 z rows (32 float4 each): 2 float4 per thread
        #pragma unroll
        for (int j = 0; j < 2; j++) {
            int idx = t + j * 256;
            int row = idx >> 5, col = idx & 31;
            int b = b_s[row];
            float4 zv = make_float4(0.f, 0.f, 0.f, 0.f);
            if (b >= 0) zv = ((const float4*)(z + (size_t)b * H + h0))[col];
            ((float4*)&z_s[row][0])[col] = zv;
        }
        __syncthreads();

        float acc[SPQ] = {0.f, 0.f, 0.f, 0.f};
        #pragma unroll
        for (int i = 0; i < HA / 4; i++) {
            #pragma unroll
            for (int s = 0; s < SPQ; s++) {
                float4 zv = ((const float4*)&z_s[q * SPQ + s][0])[i];  // broadcast
                acc[s] += vr[4*i+0] * zv.x + vr[4*i+1] * zv.y
                        + vr[4*i+2] * zv.z + vr[4*i+3] * zv.w;
            }
        }
        #pragma unroll
        for (int s = 0; s < SPQ; s++) {
            int b = b_s[q * SPQ + s];
            if (b >= 0) atomicAdd(&g_proj[b][r], acc[s]);
        }
    }
}

// -------------------------------------------------------------------------
// 4) out[b][h] = z[b][h] + sum_r u[l][h][r] * proj[b][r]
//    grid = (NL, NCB, DSPLIT), block = 128. u row in registers, reused over
//    DSB samples per sync-batch (80% FFMA inner loop).
__global__ __launch_bounds__(128) void delta_kernel(const float* __restrict__ z,
                                                    const float* __restrict__ u,
                                                    float* __restrict__ out) {
    __shared__ float4 proj_s[DSB][R / 4];   // 2KB

    const int l  = blockIdx.x;
    const int h0 = blockIdx.y * HB;
    const int zs = blockIdx.z;
    const int t  = threadIdx.x;
    const int h  = h0 + t;

    const int n = g_count[l];
    if (n == 0) return;

    // u row for this h into registers (16 x float4; warp covers a contiguous 8KB)
    float4 u_r[16];
    {
        const float4* ubase = (const float4*)(u + ((size_t)l * H + h) * R);
        #pragma unroll
        for (int i = 0; i < 16; i++) u_r[i] = ubase[i];
    }

    const int nb = (n + DSPLIT * DSB - 1) / (DSPLIT * DSB);

    for (int k = 0; k < nb; k++) {
        // uniform per-batch sample indices (L1 broadcast, no smem needed)
        int bidx[DSB];
        #pragma unroll
        for (int s = 0; s < DSB; s++) {
            int sg = zs + DSPLIT * (k * DSB + s);
            bidx[s] = (sg < n) ? g_bucket[l][sg] : -1;
        }
        __syncthreads();            // protect proj_s reuse
        {
            int s = t >> 4, c = t & 15;        // 128 threads = 8 samples x 16 vecs
            int b = bidx[s];
            if (b >= 0) proj_s[s][c] = ((const float4*)&g_proj[b][0])[c];
        }
        __syncthreads();

        float acc[DSB];
        #pragma unroll
        for (int s = 0; s < DSB; s++) acc[s] = 0.f;

        #pragma unroll
        for (int i = 0; i < 16; i++) {
            float4 uu = u_r[i];
            #pragma unroll
            for (int s = 0; s < DSB; s++) {
                float4 p = proj_s[s][i];       // broadcast LDS.128
                acc[s] += uu.x * p.x + uu.y * p.y + uu.z * p.z + uu.w * p.w;
            }
        }

        #pragma unroll
        for (int s = 0; s < DSB; s++) {
            int b = bidx[s];
            if (b >= 0) {
                size_t idx = (size_t)b * H + h;
                out[idx] = z[idx] + acc[s];
            }
        }
    }
}

// -------------------------------------------------------------------------
extern "C" void kernel_launch(void* const* d_in, const int* in_sizes, int n_in,
                              void* d_out, int out_size) {
    const float* z         = (const float*)d_in[0];
    const int*   layer_ids = (const int*)d_in[1];
    const float* u         = (const float*)d_in[2];
    const float* v         = (const float*)d_in[3];
    float*       out       = (float*)d_out;

    init_kernel<<<256, 256>>>();
    bucket_kernel<<<(BSZ + 255) / 256, 256>>>(layer_ids);
    proj_kernel<<<dim3(NL, NCA, PSPLIT), 256>>>(z, v);
    delta_kernel<<<dim3(NL, NCB, DSPLIT), 128>>>(z, u, out);
}

// round 4
// speedup vs baseline: 1.3707x; 1.0649x over previous
#include <cuda_runtime.h>

// Problem constants
#define NL   32
#define H    2048
#define R    64
#define BSZ  2048

// proj phase: grid (NL, NKC); k-dim (h) chunked by KH
#define KH   64
#define NKC  (H / KH)      // 32
#define SC   64            // samples per chunk (both phases)

// delta phase: grid (NL, NHC); output h chunked by HO
#define HO   64
#define NHC  (H / HO)      // 32

// Scratch (device globals; no allocation allowed)
__device__ int   g_count[NL];
__device__ int   g_bucket[NL][BSZ];
__device__ float g_projp[NKC][BSZ][R];   // 16 MB partials (fully rewritten each run)
__device__ float g_proj[BSZ][R];

// -------------------------------------------------------------------------
__global__ void init_counts() {
    if (threadIdx.x < NL) g_count[threadIdx.x] = 0;
}

__global__ void bucket_kernel(const int* __restrict__ layer_ids) {
    int b = blockIdx.x * blockDim.x + threadIdx.x;
    if (b < BSZ) {
        int l = layer_ids[b];
        int pos = atomicAdd(&g_count[l], 1);
        g_bucket[l][pos] = b;
    }
}

// -------------------------------------------------------------------------
// proj partial: projp[hc][b][r] = sum_{h in chunk hc} v[l][h][r] * z[b][h]
// grid (NL, NKC), block 128. Tile: SC samples x R outputs, k = KH.
// Thread (tx = r-quad 0..15, ty = s-oct 0..7): 8 samples x 4 r.
__global__ __launch_bounds__(128, 6) void proj_kernel(const float* __restrict__ z,
                                                      const float* __restrict__ v) {
    __shared__ float v_s[KH][R];        // [h][r]  16 KB
    __shared__ float z_t[KH][SC + 8];   // [h][s] transposed, 18 KB
    __shared__ int   b_s[SC];

    const int l  = blockIdx.x;
    const int hc = blockIdx.y;
    const int h0 = hc * KH;
    const int t  = threadIdx.x;
    const int tx = t & 15;
    const int ty = t >> 4;

    const int n = g_count[l];
    if (n == 0) return;

    // stage v chunk (coalesced): KH*R/4 = 1024 float4
    {
        const float4* vb  = (const float4*)(v + ((size_t)l * H + h0) * R);
        float4*       vs4 = (float4*)&v_s[0][0];
        #pragma unroll
        for (int i = 0; i < 8; i++) vs4[t + i * 128] = vb[t + i * 128];
    }

    const int nc = (n + SC - 1) / SC;
    for (int c = 0; c < nc; c++) {
        __syncthreads();                 // protects z_t/b_s reuse (+ v_s on c==0)
        if (t < SC) {
            int sg = c * SC + t;
            b_s[t] = (sg < n) ? g_bucket[l][sg] : -1;
        }
        __syncthreads();
        // stage z transposed: SC samples x KH h
        #pragma unroll
        for (int i = 0; i < 8; i++) {
            int idx = t + i * 128;
            int s = idx >> 4, hq = idx & 15;
            int b = b_s[s];
            float4 zv = make_float4(0.f, 0.f, 0.f, 0.f);
            if (b >= 0) zv = ((const float4*)(z + (size_t)b * H + h0))[hq];
            z_t[hq * 4 + 0][s] = zv.x;
            z_t[hq * 4 + 1][s] = zv.y;
            z_t[hq * 4 + 2][s] = zv.z;
            z_t[hq * 4 + 3][s] = zv.w;
        }
        __syncthreads();

        float4 acc[8];
        #pragma unroll
        for (int s8 = 0; s8 < 8; s8++) acc[s8] = make_float4(0.f, 0.f, 0.f, 0.f);

        #pragma unroll 8
        for (int h = 0; h < KH; h++) {
            const float4 vv = *(const float4*)&v_s[h][tx * 4];
            const float4 za = *(const float4*)&z_t[h][ty * 8];
            const float4 zb = *(const float4*)&z_t[h][ty * 8 + 4];
            acc[0].x += za.x * vv.x; acc[0].y += za.x * vv.y; acc[0].z += za.x * vv.z; acc[0].w += za.x * vv.w;
            acc[1].x += za.y * vv.x; acc[1].y += za.y * vv.y; acc[1].z += za.y * vv.z; acc[1].w += za.y * vv.w;
            acc[2].x += za.z * vv.x; acc[2].y += za.z * vv.y; acc[2].z += za.z * vv.z; acc[2].w += za.z * vv.w;
            acc[3].x += za.w * vv.x; acc[3].y += za.w * vv.y; acc[3].z += za.w * vv.z; acc[3].w += za.w * vv.w;
            acc[4].x += zb.x * vv.x; acc[4].y += zb.x * vv.y; acc[4].z += zb.x * vv.z; acc[4].w += zb.x * vv.w;
            acc[5].x += zb.y * vv.x; acc[5].y += zb.y * vv.y; acc[5].z += zb.y * vv.z; acc[5].w += zb.y * vv.w;
            acc[6].x += zb.z * vv.x; acc[6].y += zb.z * vv.y; acc[6].z += zb.z * vv.z; acc[6].w += zb.z * vv.w;
            acc[7].x += zb.w * vv.x; acc[7].y += zb.w * vv.y; acc[7].z += zb.w * vv.z; acc[7].w += zb.w * vv.w;
        }

        #pragma unroll
        for (int s8 = 0; s8 < 8; s8++) {
            int b = b_s[ty * 8 + s8];
            if (b >= 0)
                *(float4*)&g_projp[hc][b][tx * 4] = acc[s8];
        }
    }
}

// -------------------------------------------------------------------------
// reduce partials: g_proj[b][r] = sum_c g_projp[c][b][r]
__global__ __launch_bounds__(256) void reduce_kernel() {
    int idx = blockIdx.x * blockDim.x + threadIdx.x;   // 0 .. BSZ*16
    if (idx >= BSZ * (R / 4)) return;
    int b = idx >> 4, rq = idx & 15;
    float4 s = make_float4(0.f, 0.f, 0.f, 0.f);
    #pragma unroll
    for (int c = 0; c < NKC; c++) {
        float4 p = ((const float4*)&g_projp[c][b][0])[rq];
        s.x += p.x; s.y += p.y; s.z += p.z; s.w += p.w;
    }
    ((float4*)&g_proj[b][0])[rq] = s;
}

// -------------------------------------------------------------------------
// delta: out[b][h] = z[b][h] + sum_r u[l][h][r] * proj[b][r]
// grid (NL, NHC), block 128. Tile: SC samples x HO h outputs, k = R.
// Thread (tx = h-quad 0..15, ty = s-oct 0..7): 8 samples x 4 h.
__global__ __launch_bounds__(128, 6) void delta_kernel(const float* __restrict__ z,
                                                       const float* __restrict__ u,
                                                       float* __restrict__ out) {
    __shared__ float u_t[R][HO + 8];    // [r][h] transposed, 18 KB
    __shared__ float p_t[R][SC + 8];    // [r][s] transposed, 18 KB
    __shared__ int   b_s[SC];

    const int l  = blockIdx.x;
    const int hc = blockIdx.y;
    const int h0 = hc * HO;
    const int t  = threadIdx.x;
    const int tx = t & 15;
    const int ty = t >> 4;

    const int n = g_count[l];
    if (n == 0) return;

    // stage u transposed: HO h-rows x R
    #pragma unroll
    for (int i = 0; i < 8; i++) {
        int idx = t + i * 128;
        int h = idx >> 4, rq = idx & 15;
        float4 uv = ((const float4*)(u + ((size_t)l * H + h0 + h) * R))[rq];
        u_t[rq * 4 + 0][h] = uv.x;
        u_t[rq * 4 + 1][h] = uv.y;
        u_t[rq * 4 + 2][h] = uv.z;
        u_t[rq * 4 + 3][h] = uv.w;
    }

    const int nc = (n + SC - 1) / SC;
    for (int c = 0; c < nc; c++) {
        __syncthreads();                 // protects p_t/b_s reuse (+ u_t on c==0)
        if (t < SC) {
            int sg = c * SC + t;
            b_s[t] = (sg < n) ? g_bucket[l][sg] : -1;
        }
        __syncthreads();
        // stage proj transposed: SC samples x R
        #pragma unroll
        for (int i = 0; i < 8; i++) {
            int idx = t + i * 128;
            int s = idx >> 4, rq = idx & 15;
            int b = b_s[s];
            float4 pv = make_float4(0.f, 0.f, 0.f, 0.f);
            if (b >= 0) pv = ((const float4*)&g_proj[b][0])[rq];
            p_t[rq * 4 + 0][s] = pv.x;
            p_t[rq * 4 + 1][s] = pv.y;
            p_t[rq * 4 + 2][s] = pv.z;
            p_t[rq * 4 + 3][s] = pv.w;
        }
        __syncthreads();

        float4 acc[8];
        #pragma unroll
        for (int s8 = 0; s8 < 8; s8++) acc[s8] = make_float4(0.f, 0.f, 0.f, 0.f);

        #pragma unroll 8
        for (int r = 0; r < R; r++) {
            const float4 uu = *(const float4*)&u_t[r][tx * 4];
            const float4 pa = *(const float4*)&p_t[r][ty * 8];
            const float4 pb = *(const float4*)&p_t[r][ty * 8 + 4];
            acc[0].x += pa.x * uu.x; acc[0].y += pa.x * uu.y; acc[0].z += pa.x * uu.z; acc[0].w += pa.x * uu.w;
            acc[1].x += pa.y * uu.x; acc[1].y += pa.y * uu.y; acc[1].z += pa.y * uu.z; acc[1].w += pa.y * uu.w;
            acc[2].x += pa.z * uu.x; acc[2].y += pa.z * uu.y; acc[2].z += pa.z * uu.z; acc[2].w += pa.z * uu.w;
            acc[3].x += pa.w * uu.x; acc[3].y += pa.w * uu.y; acc[3].z += pa.w * uu.z; acc[3].w += pa.w * uu.w;
            acc[4].x += pb.x * uu.x; acc[4].y += pb.x * uu.y; acc[4].z += pb.x * uu.z; acc[4].w += pb.x * uu.w;
            acc[5].x += pb.y * uu.x; acc[5].y += pb.y * uu.y; acc[5].z += pb.y * uu.z; acc[5].w += pb.y * uu.w;
            acc[6].x += pb.z * uu.x; acc[6].y += pb.z * uu.y; acc[6].z += pb.z * uu.z; acc[6].w += pb.z * uu.w;
            acc[7].x += pb.w * uu.x; acc[7].y += pb.w * uu.y; acc[7].z += pb.w * uu.z; acc[7].w += pb.w * uu.w;
        }

        // epilogue: out = z + acc
        #pragma unroll
        for (int s8 = 0; s8 < 8; s8++) {
            int b = b_s[ty * 8 + s8];
            if (b >= 0) {
                const size_t base = (size_t)b * H + h0 + tx * 4;
                const float4 zz = *(const float4*)(z + base);
                float4 o;
                o.x = zz.x + acc[s8].x;
                o.y = zz.y + acc[s8].y;
                o.z = zz.z + acc[s8].z;
                o.w = zz.w + acc[s8].w;
                *(float4*)(out + base) = o;
            }
        }
    }
}

// -------------------------------------------------------------------------
extern "C" void kernel_launch(void* const* d_in, const int* in_sizes, int n_in,
                              void* d_out, int out_size) {
    const float* z         = (const float*)d_in[0];
    const int*   layer_ids = (const int*)d_in[1];
    const float* u         = (const float*)d_in[2];
    const float* v         = (const float*)d_in[3];
    float*       out       = (float*)d_out;

    init_counts<<<1, 32>>>();
    bucket_kernel<<<(BSZ + 255) / 256, 256>>>(layer_ids);
    proj_kernel<<<dim3(NL, NKC), 128>>>(z, v);
    reduce_kernel<<<(BSZ * (R / 4) + 255) / 256, 256>>>();
    delta_kernel<<<dim3(NL, NHC), 128>>>(z, u, out);
}

// round 6
// speedup vs baseline: 1.4258x; 1.0402x over previous
#include <cuda_runtime.h>

// Problem constants
#define NL   32
#define H    2048
#define R    64
#define BSZ  2048

// proj phase: grid (NL, NKC); k-dim (h) chunked by KH
#define KH   64
#define NKC  (H / KH)      // 32
#define SC   64            // samples per chunk (both phases)

// delta phase: grid (NL, NHC); output h chunked by HO
#define HO   64
#define NHC  (H / HO)      // 32

// Scratch (device globals; no allocation allowed)
__device__ int   g_count[NL];
__device__ int   g_bucket[NL][BSZ];
__device__ float g_projp[NKC][BSZ][R];   // 16 MB partials (fully rewritten each run)
__device__ float g_proj[BSZ][R];

// ---- packed f32x2 helpers (FFMA2 path on sm_103a fma pipe) -----------------
typedef unsigned long long u64t;

__device__ __forceinline__ u64t dup2(float x) {
    u64t r;
    asm("mov.b64 %0, {%1, %1};" : "=l"(r) : "f"(x));
    return r;
}
__device__ __forceinline__ void fma2(u64t& d, u64t a, u64t b) {
    asm("fma.rn.f32x2 %0, %1, %2, %0;" : "+l"(d) : "l"(a), "l"(b));
}
__device__ __forceinline__ void add2(u64t& d, u64t a) {
    asm("add.rn.f32x2 %0, %0, %1;" : "+l"(d) : "l"(a));
}
__device__ __forceinline__ float2 unpk(u64t v) {
    float2 f;
    asm("mov.b64 {%0, %1}, %2;" : "=f"(f.x), "=f"(f.y) : "l"(v));
    return f;
}

// -------------------------------------------------------------------------
__global__ void init_counts() {
    if (threadIdx.x < NL) g_count[threadIdx.x] = 0;
}

__global__ void bucket_kernel(const int* __restrict__ layer_ids) {
    int b = blockIdx.x * blockDim.x + threadIdx.x;
    if (b < BSZ) {
        int l = layer_ids[b];
        int pos = atomicAdd(&g_count[l], 1);
        g_bucket[l][pos] = b;
    }
}

// -------------------------------------------------------------------------
// proj partial: projp[hc][b][r] = sum_{h in chunk hc} v[l][h][r] * z[b][h]
// grid (NL, NKC), block 128. Tile: SC samples x R outputs, k = KH.
// Thread (tx 0..15 = r-quad, ty 0..7 = sample-oct): 8 samples x 4 r,
// accumulated as 4x4 f32x2 (sample-pairs packed straight from smem).
__global__ __launch_bounds__(128, 6) void proj_kernel(const float* __restrict__ z,
                                                      const float* __restrict__ v) {
    __shared__ float v_s[KH][R];        // [h][r]  16 KB
    __shared__ float z_t[KH][SC + 8];   // [h][s]  18 KB
    __shared__ int   b_s[SC];

    const int l  = blockIdx.x;
    const int hc = blockIdx.y;
    const int h0 = hc * KH;
    const int t  = threadIdx.x;
    const int tx = t & 15;
    const int ty = t >> 4;

    const int n = g_count[l];
    if (n == 0) return;

    // stage v chunk (coalesced): KH*R/4 = 1024 float4
    {
        const float4* vb  = (const float4*)(v + ((size_t)l * H + h0) * R);
        float4*       vs4 = (float4*)&v_s[0][0];
        #pragma unroll
        for (int i = 0; i < 8; i++) vs4[t + i * 128] = vb[t + i * 128];
    }

    const int nc = (n + SC - 1) / SC;
    for (int c = 0; c < nc; c++) {
        __syncthreads();                 // protects z_t/b_s reuse (+ v_s on c==0)
        if (t < SC) {
            int sg = c * SC + t;
            b_s[t] = (sg < n) ? g_bucket[l][sg] : -1;
        }
        __syncthreads();
        // stage z transposed: SC samples x KH h
        #pragma unroll
        for (int i = 0; i < 8; i++) {
            int idx = t + i * 128;
            int s = idx >> 4, hq = idx & 15;
            int b = b_s[s];
            float4 zv = make_float4(0.f, 0.f, 0.f, 0.f);
            if (b >= 0) zv = ((const float4*)(z + (size_t)b * H + h0))[hq];
            z_t[hq * 4 + 0][s] = zv.x;
            z_t[hq * 4 + 1][s] = zv.y;
            z_t[hq * 4 + 2][s] = zv.z;
            z_t[hq * 4 + 3][s] = zv.w;
        }
        __syncthreads();

        u64t acc[4][4];                  // [r][sample-pair]
        #pragma unroll
        for (int i = 0; i < 4; i++)
            #pragma unroll
            for (int j = 0; j < 4; j++) acc[i][j] = 0ull;

        #pragma unroll 8
        for (int h = 0; h < KH; h++) {
            const float4 vv = *(const float4*)&v_s[h][tx * 4];
            const u64t vd0 = dup2(vv.x), vd1 = dup2(vv.y);
            const u64t vd2 = dup2(vv.z), vd3 = dup2(vv.w);
            const ulonglong2 za = *(const ulonglong2*)&z_t[h][ty * 8];
            const ulonglong2 zb = *(const ulonglong2*)&z_t[h][ty * 8 + 4];
            fma2(acc[0][0], vd0, za.x); fma2(acc[0][1], vd0, za.y);
            fma2(acc[0][2], vd0, zb.x); fma2(acc[0][3], vd0, zb.y);
            fma2(acc[1][0], vd1, za.x); fma2(acc[1][1], vd1, za.y);
            fma2(acc[1][2], vd1, zb.x); fma2(acc[1][3], vd1, zb.y);
            fma2(acc[2][0], vd2, za.x); fma2(acc[2][1], vd2, za.y);
            fma2(acc[2][2], vd2, zb.x); fma2(acc[2][3], vd2, zb.y);
            fma2(acc[3][0], vd3, za.x); fma2(acc[3][1], vd3, za.y);
            fma2(acc[3][2], vd3, zb.x); fma2(acc[3][3], vd3, zb.y);
        }

        #pragma unroll
        for (int s8 = 0; s8 < 8; s8++) {
            int b = b_s[ty * 8 + s8];
            if (b >= 0) {
                const int sp = s8 >> 1;
                const float2 a0 = unpk(acc[0][sp]);
                const float2 a1 = unpk(acc[1][sp]);
                const float2 a2 = unpk(acc[2][sp]);
                const float2 a3 = unpk(acc[3][sp]);
                float4 o = (s8 & 1) ? make_float4(a0.y, a1.y, a2.y, a3.y)
                                    : make_float4(a0.x, a1.x, a2.x, a3.x);
                *(float4*)&g_projp[hc][b][tx * 4] = o;
            }
        }
    }
}

// -------------------------------------------------------------------------
// reduce partials: g_proj[b][r] = sum_c g_projp[c][b][r]
// One f32x2 per thread -> 65536 threads / 256 blocks (occupancy fix).
__global__ __launch_bounds__(256) void reduce_kernel() {
    int idx = blockIdx.x * blockDim.x + threadIdx.x;   // < BSZ * R/2
    int b = idx >> 5, rp = idx & 31;
    u64t s = 0ull;
    #pragma unroll
    for (int c = 0; c < NKC; c++)
        add2(s, *(const u64t*)&g_projp[c][b][rp * 2]);
    *(u64t*)&g_proj[b][rp * 2] = s;
}

// -------------------------------------------------------------------------
// delta: out[b][h] = z[b][h] + sum_r u[l][h][r] * proj[b][r]
// grid (NL, NHC), block 128. Tile: SC samples x HO h, k = R. f32x2 packed.
__global__ __launch_bounds__(128, 6) void delta_kernel(const float* __restrict__ z,
                                                       const float* __restrict__ u,
                                                       float* __restrict__ out) {
    __shared__ float u_t[R][HO + 8];    // [r][h]  18 KB
    __shared__ float p_t[R][SC + 8];    // [r][s]  18 KB
    __shared__ int   b_s[SC];

    const int l  = blockIdx.x;
    const int hc = blockIdx.y;
    const int h0 = hc * HO;
    const int t  = threadIdx.x;
    const int tx = t & 15;
    const int ty = t >> 4;

    const int n = g_count[l];
    if (n == 0) return;

    // stage u transposed: HO h-rows x R
    #pragma unroll
    for (int i = 0; i < 8; i++) {
        int idx = t + i * 128;
        int h = idx >> 4, rq = idx & 15;
        float4 uv = ((const float4*)(u + ((size_t)l * H + h0 + h) * R))[rq];
        u_t[rq * 4 + 0][h] = uv.x;
        u_t[rq * 4 + 1][h] = uv.y;
        u_t[rq * 4 + 2][h] = uv.z;
        u_t[rq * 4 + 3][h] = uv.w;
    }

    const int nc = (n + SC - 1) / SC;
    for (int c = 0; c < nc; c++) {
        __syncthreads();                 // protects p_t/b_s reuse (+ u_t on c==0)
        if (t < SC) {
            int sg = c * SC + t;
            b_s[t] = (sg < n) ? g_bucket[l][sg] : -1;
        }
        __syncthreads();
        // stage proj transposed: SC samples x R
        #pragma unroll
        for (int i = 0; i < 8; i++) {
            int idx = t + i * 128;
            int s = idx >> 4, rq = idx & 15;
            int b = b_s[s];
            float4 pv = make_float4(0.f, 0.f, 0.f, 0.f);
            if (b >= 0) pv = ((const float4*)&g_proj[b][0])[rq];
            p_t[rq * 4 + 0][s] = pv.x;
            p_t[rq * 4 + 1][s] = pv.y;
            p_t[rq * 4 + 2][s] = pv.z;
            p_t[rq * 4 + 3][s] = pv.w;
        }
        __syncthreads();

        u64t acc[4][4];                  // [h][sample-pair]
        #pragma unroll
        for (int i = 0; i < 4; i++)
            #pragma unroll
            for (int j = 0; j < 4; j++) acc[i][j] = 0ull;

        #pragma unroll 8
        for (int r = 0; r < R; r++) {
            const float4 uu = *(const float4*)&u_t[r][tx * 4];
            const u64t ud0 = dup2(uu.x), ud1 = dup2(uu.y);
            const u64t ud2 = dup2(uu.z), ud3 = dup2(uu.w);
            const ulonglong2 pa = *(const ulonglong2*)&p_t[r][ty * 8];
            const ulonglong2 pb = *(const ulonglong2*)&p_t[r][ty * 8 + 4];
            fma2(acc[0][0], ud0, pa.x); fma2(acc[0][1], ud0, pa.y);
            fma2(acc[0][2], ud0, pb.x); fma2(acc[0][3], ud0, pb.y);
            fma2(acc[1][0], ud1, pa.x); fma2(acc[1][1], ud1, pa.y);
            fma2(acc[1][2], ud1, pb.x); fma2(acc[1][3], ud1, pb.y);
            fma2(acc[2][0], ud2, pa.x); fma2(acc[2][1], ud2, pa.y);
            fma2(acc[2][2], ud2, pb.x); fma2(acc[2][3], ud2, pb.y);
            fma2(acc[3][0], ud3, pa.x); fma2(acc[3][1], ud3, pa.y);
            fma2(acc[3][2], ud3, pb.x); fma2(acc[3][3], ud3, pb.y);
        }

        // epilogue: out = z + acc
        #pragma unroll
        for (int s8 = 0; s8 < 8; s8++) {
            int b = b_s[ty * 8 + s8];
            if (b >= 0) {
                const int sp = s8 >> 1;
                const float2 a0 = unpk(acc[0][sp]);
                const float2 a1 = unpk(acc[1][sp]);
                const float2 a2 = unpk(acc[2][sp]);
                const float2 a3 = unpk(acc[3][sp]);
                const size_t base = (size_t)b * H + h0 + tx * 4;
                const float4 zz = *(const float4*)(z + base);
                float4 o;
                if (s8 & 1) {
                    o.x = zz.x + a0.y; o.y = zz.y + a1.y;
                    o.z = zz.z + a2.y; o.w = zz.w + a3.y;
                } else {
                    o.x = zz.x + a0.x; o.y = zz.y + a1.x;
                    o.z = zz.z + a2.x; o.w = zz.w + a3.x;
                }
                *(float4*)(out + base) = o;
            }
        }
    }
}

// -------------------------------------------------------------------------
extern "C" void kernel_launch(void* const* d_in, const int* in_sizes, int n_in,
                              void* d_out, int out_size) {
    const float* z         = (const float*)d_in[0];
    const int*   layer_ids = (const int*)d_in[1];
    const float* u         = (const float*)d_in[2];
    const float* v         = (const float*)d_in[3];
    float*       out       = (float*)d_out;

    init_counts<<<1, 32>>>();
    bucket_kernel<<<(BSZ + 255) / 256, 256>>>(layer_ids);
    proj_kernel<<<dim3(NL, NKC), 128>>>(z, v);
    reduce_kernel<<<(BSZ * (R / 2)) / 256, 256>>>();
    delta_kernel<<<dim3(NL, NHC), 128>>>(z, u, out);
}

// round 8
// speedup vs baseline: 1.7476x; 1.2257x over previous
#include <cuda_runtime.h>

// Problem constants
#define NL   32
#define H    2048
#define R    64
#define BSZ  2048

// proj phase: grid (NL, NKC); k-dim (h) chunked by KH
#define KH   64
#define NKC  (H / KH)      // 32
#define SC   64            // samples per chunk (both phases)

// delta phase: grid (NL, NHC); output h chunked by HO
#define HO   64
#define NHC  (H / HO)      // 32

// Scratch (device globals; no allocation allowed)
__device__ int   g_count[NL];
__device__ int   g_bucket[NL][BSZ];
__device__ float g_projp[NKC][BSZ][R];   // 16 MB partials (fully rewritten each run)
__device__ float g_proj2[2][BSZ][R];     // half-sums

// ---- packed f32x2 helpers (FFMA2 path on sm_103a fma pipe) -----------------
typedef unsigned long long u64t;

__device__ __forceinline__ u64t dup2(float x) {
    u64t r;
    asm("mov.b64 %0, {%1, %1};" : "=l"(r) : "f"(x));
    return r;
}
__device__ __forceinline__ void fma2(u64t& d, u64t a, u64t b) {
    asm("fma.rn.f32x2 %0, %1, %2, %0;" : "+l"(d) : "l"(a), "l"(b));
}
__device__ __forceinline__ void add2(u64t& d, u64t a) {
    asm("add.rn.f32x2 %0, %0, %1;" : "+l"(d) : "l"(a));
}
__device__ __forceinline__ float2 unpk(u64t v) {
    float2 f;
    asm("mov.b64 {%0, %1}, %2;" : "=f"(f.x), "=f"(f.y) : "l"(v));
    return f;
}

// -------------------------------------------------------------------------
__global__ void init_counts() {
    if (threadIdx.x < NL) g_count[threadIdx.x] = 0;
}

__global__ void bucket_kernel(const int* __restrict__ layer_ids) {
    int b = blockIdx.x * blockDim.x + threadIdx.x;
    if (b < BSZ) {
        int l = layer_ids[b];
        int pos = atomicAdd(&g_count[l], 1);
        g_bucket[l][pos] = b;
    }
}

// -------------------------------------------------------------------------
// proj partial: projp[hc][b][r] = sum_{h in chunk hc} v[l][h][r] * z[b][h]
// grid (NL, NKC), block 128. Tile: SC samples x R outputs, k = KH.
// Staging remap: each lane owns a distinct sample-column -> conflict-free STS.
__global__ __launch_bounds__(128, 6) void proj_kernel(const float* __restrict__ z,
                                                      const float* __restrict__ v) {
    __shared__ float v_s[KH][R];         // [h][r]  16 KB
    __shared__ float z_t[KH][SC + 4];    // [h][s]  17 KB (stride 68: 16B-aligned rows)
    __shared__ int   b_s[SC];

    const int l  = blockIdx.x;
    const int hc = blockIdx.y;
    const int h0 = hc * KH;
    const int t  = threadIdx.x;
    const int tx = t & 15;
    const int ty = t >> 4;

    const int n = g_count[l];
    if (n == 0) return;

    // stage v chunk (coalesced): KH*R/4 = 1024 float4
    {
        const float4* vb  = (const float4*)(v + ((size_t)l * H + h0) * R);
        float4*       vs4 = (float4*)&v_s[0][0];
        #pragma unroll
        for (int i = 0; i < 8; i++) vs4[t + i * 128] = vb[t + i * 128];
    }

    const int nc = (n + SC - 1) / SC;
    for (int c = 0; c < nc; c++) {
        __syncthreads();                 // protects z_t/b_s reuse (+ v_s on c==0)
        if (t < SC) {
            int sg = c * SC + t;
            b_s[t] = (sg < n) ? g_bucket[l][sg] : -1;
        }
        __syncthreads();
        // stage z transposed: lane -> distinct column s (no STS conflicts)
        #pragma unroll
        for (int i = 0; i < 8; i++) {
            int idx = t + i * 128;
            int s  = idx & 63;           // distinct per lane
            int hq = idx >> 6;           // 0..15
            int b = b_s[s];
            float4 zv = make_float4(0.f, 0.f, 0.f, 0.f);
            if (b >= 0) zv = ((const float4*)(z + (size_t)b * H + h0))[hq];
            z_t[hq * 4 + 0][s] = zv.x;
            z_t[hq * 4 + 1][s] = zv.y;
            z_t[hq * 4 + 2][s] = zv.z;
            z_t[hq * 4 + 3][s] = zv.w;
        }
        __syncthreads();

        u64t acc[4][4];                  // [r][sample-pair]
        #pragma unroll
        for (int i = 0; i < 4; i++)
            #pragma unroll
            for (int j = 0; j < 4; j++) acc[i][j] = 0ull;

        #pragma unroll 8
        for (int h = 0; h < KH; h++) {
            const float4 vv = *(const float4*)&v_s[h][tx * 4];
            const u64t vd0 = dup2(vv.x), vd1 = dup2(vv.y);
            const u64t vd2 = dup2(vv.z), vd3 = dup2(vv.w);
            const ulonglong2 za = *(const ulonglong2*)&z_t[h][ty * 8];
            const ulonglong2 zb = *(const ulonglong2*)&z_t[h][ty * 8 + 4];
            fma2(acc[0][0], vd0, za.x); fma2(acc[0][1], vd0, za.y);
            fma2(acc[0][2], vd0, zb.x); fma2(acc[0][3], vd0, zb.y);
            fma2(acc[1][0], vd1, za.x); fma2(acc[1][1], vd1, za.y);
            fma2(acc[1][2], vd1, zb.x); fma2(acc[1][3], vd1, zb.y);
            fma2(acc[2][0], vd2, za.x); fma2(acc[2][1], vd2, za.y);
            fma2(acc[2][2], vd2, zb.x); fma2(acc[2][3], vd2, zb.y);
            fma2(acc[3][0], vd3, za.x); fma2(acc[3][1], vd3, za.y);
            fma2(acc[3][2], vd3, zb.x); fma2(acc[3][3], vd3, zb.y);
        }

        #pragma unroll
        for (int s8 = 0; s8 < 8; s8++) {
            int b = b_s[ty * 8 + s8];
            if (b >= 0) {
                const int sp = s8 >> 1;
                const float2 a0 = unpk(acc[0][sp]);
                const float2 a1 = unpk(acc[1][sp]);
                const float2 a2 = unpk(acc[2][sp]);
                const float2 a3 = unpk(acc[3][sp]);
                float4 o = (s8 & 1) ? make_float4(a0.y, a1.y, a2.y, a3.y)
                                    : make_float4(a0.x, a1.x, a2.x, a3.x);
                *(float4*)&g_projp[hc][b][tx * 4] = o;
            }
        }
    }
}

// -------------------------------------------------------------------------
// reduce: g_proj2[half][b][r] = sum over 16 chunks. 131072 threads,
// 4 independent f32x2 accumulator chains -> deep MLP.
__global__ __launch_bounds__(256) void reduce_kernel() {
    int idx = blockIdx.x * blockDim.x + threadIdx.x;   // < 2 * BSZ * 32
    int hf  = idx >> 16;
    int rem = idx & 65535;
    int b   = rem >> 5;
    int rp  = rem & 31;
    const int c0 = hf * 16;

    u64t a0 = 0ull, a1 = 0ull, a2 = 0ull, a3 = 0ull;
    #pragma unroll
    for (int c = 0; c < 4; c++) {
        add2(a0, *(const u64t*)&g_projp[c0 + 4*c + 0][b][rp * 2]);
        add2(a1, *(const u64t*)&g_projp[c0 + 4*c + 1][b][rp * 2]);
        add2(a2, *(const u64t*)&g_projp[c0 + 4*c + 2][b][rp * 2]);
        add2(a3, *(const u64t*)&g_projp[c0 + 4*c + 3][b][rp * 2]);
    }
    add2(a0, a1); add2(a2, a3); add2(a0, a2);
    *(u64t*)&g_proj2[hf][b][rp * 2] = a0;
}

// -------------------------------------------------------------------------
// delta: out[b][h] = z[b][h] + sum_r u[l][h][r] * proj[b][r]
// grid (NL, NHC), block 128. Conflict-free staging as in proj; proj halves
// summed during staging.
__global__ __launch_bounds__(128, 6) void delta_kernel(const float* __restrict__ z,
                                                       const float* __restrict__ u,
                                                       float* __restrict__ out) {
    __shared__ float u_t[R][HO + 4];    // [r][h]  17 KB
    __shared__ float p_t[R][SC + 4];    // [r][s]  17 KB
    __shared__ int   b_s[SC];

    const int l  = blockIdx.x;
    const int hc = blockIdx.y;
    const int h0 = hc * HO;
    const int t  = threadIdx.x;
    const int tx = t & 15;
    const int ty = t >> 4;

    const int n = g_count[l];
    if (n == 0) return;

    // stage u transposed: lane -> distinct h column (no STS conflicts)
    #pragma unroll
    for (int i = 0; i < 8; i++) {
        int idx = t + i * 128;
        int h  = idx & 63;
        int rq = idx >> 6;
        float4 uv = ((const float4*)(u + ((size_t)l * H + h0 + h) * R))[rq];
        u_t[rq * 4 + 0][h] = uv.x;
        u_t[rq * 4 + 1][h] = uv.y;
        u_t[rq * 4 + 2][h] = uv.z;
        u_t[rq * 4 + 3][h] = uv.w;
    }

    const int nc = (n + SC - 1) / SC;
    for (int c = 0; c < nc; c++) {
        __syncthreads();                 // protects p_t/b_s reuse (+ u_t on c==0)
        if (t < SC) {
            int sg = c * SC + t;
            b_s[t] = (sg < n) ? g_bucket[l][sg] : -1;
        }
        __syncthreads();
        // stage proj transposed (sum of 2 halves): lane -> distinct s column
        #pragma unroll
        for (int i = 0; i < 8; i++) {
            int idx = t + i * 128;
            int s  = idx & 63;
            int rq = idx >> 6;
            int b = b_s[s];
            float4 pv = make_float4(0.f, 0.f, 0.f, 0.f);
            if (b >= 0) {
                float4 p0 = ((const float4*)&g_proj2[0][b][0])[rq];
                float4 p1 = ((const float4*)&g_proj2[1][b][0])[rq];
                pv.x = p0.x + p1.x; pv.y = p0.y + p1.y;
                pv.z = p0.z + p1.z; pv.w = p0.w + p1.w;
            }
            p_t[rq * 4 + 0][s] = pv.x;
            p_t[rq * 4 + 1][s] = pv.y;
            p_t[rq * 4 + 2][s] = pv.z;
            p_t[rq * 4 + 3][s] = pv.w;
        }
        __syncthreads();

        u64t acc[4][4];                  // [h][sample-pair]
        #pragma unroll
        for (int i = 0; i < 4; i++)
            #pragma unroll
            for (int j = 0; j < 4; j++) acc[i][j] = 0ull;

        #pragma unroll 8
        for (int r = 0; r < R; r++) {
            const float4 uu = *(const float4*)&u_t[r][tx * 4];
            const u64t ud0 = dup2(uu.x), ud1 = dup2(uu.y);
            const u64t ud2 = dup2(uu.z), ud3 = dup2(uu.w);
            const ulonglong2 pa = *(const ulonglong2*)&p_t[r][ty * 8];
            const ulonglong2 pb = *(const ulonglong2*)&p_t[r][ty * 8 + 4];
            fma2(acc[0][0], ud0, pa.x); fma2(acc[0][1], ud0, pa.y);
            fma2(acc[0][2], ud0, pb.x); fma2(acc[0][3], ud0, pb.y);
            fma2(acc[1][0], ud1, pa.x); fma2(acc[1][1], ud1, pa.y);
            fma2(acc[1][2], ud1, pb.x); fma2(acc[1][3], ud1, pb.y);
            fma2(acc[2][0], ud2, pa.x); fma2(acc[2][1], ud2, pa.y);
            fma2(acc[2][2], ud2, pb.x); fma2(acc[2][3], ud2, pb.y);
            fma2(acc[3][0], ud3, pa.x); fma2(acc[3][1], ud3, pa.y);
            fma2(acc[3][2], ud3, pb.x); fma2(acc[3][3], ud3, pb.y);
        }

        // epilogue: out = z + acc
        #pragma unroll
        for (int s8 = 0; s8 < 8; s8++) {
            int b = b_s[ty * 8 + s8];
            if (b >= 0) {
                const int sp = s8 >> 1;
                const float2 a0 = unpk(acc[0][sp]);
                const float2 a1 = unpk(acc[1][sp]);
                const float2 a2 = unpk(acc[2][sp]);
                const float2 a3 = unpk(acc[3][sp]);
                const size_t base = (size_t)b * H + h0 + tx * 4;
                const float4 zz = *(const float4*)(z + base);
                float4 o;
                if (s8 & 1) {
                    o.x = zz.x + a0.y; o.y = zz.y + a1.y;
                    o.z = zz.z + a2.y; o.w = zz.w + a3.y;
                } else {
                    o.x = zz.x + a0.x; o.y = zz.y + a1.x;
                    o.z = zz.z + a2.x; o.w = zz.w + a3.x;
                }
                *(float4*)(out + base) = o;
            }
        }
    }
}

// -------------------------------------------------------------------------
extern "C" void kernel_launch(void* const* d_in, const int* in_sizes, int n_in,
                              void* d_out, int out_size) {
    const float* z         = (const float*)d_in[0];
    const int*   layer_ids = (const int*)d_in[1];
    const float* u         = (const float*)d_in[2];
    const float* v         = (const float*)d_in[3];
    float*       out       = (float*)d_out;

    init_counts<<<1, 32>>>();
    bucket_kernel<<<(BSZ + 255) / 256, 256>>>(layer_ids);
    proj_kernel<<<dim3(NL, NKC), 128>>>(z, v);
    reduce_kernel<<<(2 * BSZ * 32) / 256, 256>>>();
    delta_kernel<<<dim3(NL, NHC), 128>>>(z, u, out);
}